// round 1
// baseline (speedup 1.0000x reference)
#include <cuda_runtime.h>
#include <math.h>

#define D_MODEL 2048
#define NHEADS  16
#define DK      128
#define BATCH   2
#define SEQ     2048
#define ROWS    (BATCH * SEQ)     // 4096
#define QKV_N   (3 * D_MODEL)     // 6144

// Scratch (device globals — no cudaMalloc allowed)
__device__ float g_qkv[ROWS * QKV_N];     // ~100 MB
__device__ float g_att[ROWS * D_MODEL];   // ~33 MB

// ---------------------------------------------------------------------------
// SGEMM: C[M,N] = A[M,K] @ B[K,N] + bias[N]
// 128x128 block tile, BK=16, 256 threads, 8x8 micro-tile per thread.
// M % 128 == 0, N % 128 == 0, K % 16 == 0 (true for all our shapes).
// ---------------------------------------------------------------------------
__global__ __launch_bounds__(256) void sgemm_bias(
    const float* __restrict__ A, const float* __restrict__ B,
    const float* __restrict__ bias, float* __restrict__ C,
    int M, int N, int K)
{
    __shared__ float As[16][132];   // transposed: As[k][m], padded (2-way store conflicts max)
    __shared__ float Bs[16][128];   // Bs[k][n]

    const int tid = threadIdx.x;
    const int tx = tid & 15;        // 0..15 -> N direction
    const int ty = tid >> 4;        // 0..15 -> M direction
    const int bm = blockIdx.y, bn = blockIdx.x;

    const float* Ab = A + (size_t)bm * 128 * K;
    const float* Bb = B + (size_t)bn * 128;

    float acc[8][8];
    #pragma unroll
    for (int i = 0; i < 8; i++)
        #pragma unroll
        for (int j = 0; j < 8; j++) acc[i][j] = 0.f;

    const int ar  = tid >> 2;          // 0..63 (A tile row, +64 for second half)
    const int ac4 = (tid & 3) * 4;     // 0,4,8,12 (A tile col)
    const int br  = tid >> 5;          // 0..7   (B tile row, +8 for second half)
    const int bc4 = (tid & 31) * 4;    // B tile col

    for (int kt = 0; kt < K; kt += 16) {
        // A tile: 128x16, stored transposed
        #pragma unroll
        for (int half = 0; half < 2; half++) {
            int r = ar + half * 64;
            float4 a = *(const float4*)&Ab[(size_t)r * K + kt + ac4];
            As[ac4 + 0][r] = a.x;
            As[ac4 + 1][r] = a.y;
            As[ac4 + 2][r] = a.z;
            As[ac4 + 3][r] = a.w;
        }
        // B tile: 16x128
        #pragma unroll
        for (int half = 0; half < 2; half++) {
            int r = br + half * 8;
            *(float4*)&Bs[r][bc4] = *(const float4*)&Bb[(size_t)(kt + r) * N + bc4];
        }
        __syncthreads();

        #pragma unroll
        for (int k = 0; k < 16; k++) {
            float4 a0 = *(float4*)&As[k][ty * 8];
            float4 a1 = *(float4*)&As[k][ty * 8 + 4];
            float4 b0 = *(float4*)&Bs[k][tx * 8];
            float4 b1 = *(float4*)&Bs[k][tx * 8 + 4];
            float av[8] = {a0.x, a0.y, a0.z, a0.w, a1.x, a1.y, a1.z, a1.w};
            float bv[8] = {b0.x, b0.y, b0.z, b0.w, b1.x, b1.y, b1.z, b1.w};
            #pragma unroll
            for (int i = 0; i < 8; i++)
                #pragma unroll
                for (int j = 0; j < 8; j++)
                    acc[i][j] += av[i] * bv[j];
        }
        __syncthreads();
    }

    const int col0 = bn * 128 + tx * 8;
    float bv[8];
    #pragma unroll
    for (int j = 0; j < 8; j++) bv[j] = bias[col0 + j];

    #pragma unroll
    for (int i = 0; i < 8; i++) {
        int row = bm * 128 + ty * 8 + i;
        float4 o0 = {acc[i][0] + bv[0], acc[i][1] + bv[1], acc[i][2] + bv[2], acc[i][3] + bv[3]};
        float4 o1 = {acc[i][4] + bv[4], acc[i][5] + bv[5], acc[i][6] + bv[6], acc[i][7] + bv[7]};
        *(float4*)&C[(size_t)row * N + col0]     = o0;
        *(float4*)&C[(size_t)row * N + col0 + 4] = o1;
    }
}

// ---------------------------------------------------------------------------
// Flash-style attention over interleaved QKV buffer.
// qkv layout: [B*S, 6144], head h occupies cols [h*384, h*384+384): Q|K|V of 128 each.
// Block: 64 q-rows of one (b,h). 256 threads. Online softmax, BK = 64.
// Thread (tx=tid%16, ty=tid/16):
//   scores: owns S[ty*4+i][tx*4+j] (4x4)
//   output: owns O[ty*4+i][tx*8+jd] (4x8 of the 128 dims)
// smem: Qs transposed [128][68], KV ([128][68] as K^T, reused [64][128] as V), P [64][68]
// ---------------------------------------------------------------------------
#define QS_STRIDE 68
#define P_STRIDE  68
#define ATTN_SMEM ((128 * QS_STRIDE + 128 * QS_STRIDE + 64 * P_STRIDE) * 4)

__global__ __launch_bounds__(256) void attn_kernel(
    const float* __restrict__ qkv, float* __restrict__ out)
{
    extern __shared__ float sm[];
    float* Qs = sm;                          // [128][68]  Qs[d][r]
    float* KV = sm + 128 * QS_STRIDE;        // K: [128][68] K^T[d][c];  V: [64][128]
    float* P  = sm + 2 * 128 * QS_STRIDE;    // [64][68]   P[r][k]

    const int tid = threadIdx.x;
    const int tx = tid & 15;
    const int ty = tid >> 4;
    const int qt = blockIdx.x;               // q-tile 0..31
    const int bh = blockIdx.y;               // 0..31
    const int b  = bh >> 4, h = bh & 15;

    const float* base = qkv + (size_t)b * SEQ * QKV_N + (size_t)h * (3 * DK);
    const int q0 = qt * 64;

    // per-thread load mapping: row r = tid/4 (0..63), col d = (tid&3)*4 + it*16
    const int lr  = tid >> 2;
    const int lc0 = (tid & 3) * 4;

    // Load Q tile transposed
    #pragma unroll
    for (int it = 0; it < 8; it++) {
        int d = lc0 + it * 16;
        float4 q = *(const float4*)&base[(size_t)(q0 + lr) * QKV_N + d];
        Qs[(d + 0) * QS_STRIDE + lr] = q.x;
        Qs[(d + 1) * QS_STRIDE + lr] = q.y;
        Qs[(d + 2) * QS_STRIDE + lr] = q.z;
        Qs[(d + 3) * QS_STRIDE + lr] = q.w;
    }

    float m[4], l[4], acc[4][8];
    #pragma unroll
    for (int i = 0; i < 4; i++) {
        m[i] = -1e30f; l[i] = 0.f;
        #pragma unroll
        for (int j = 0; j < 8; j++) acc[i][j] = 0.f;
    }

    const float scale = 0.08838834764831845f;   // 1/sqrt(128)

    for (int kt = 0; kt < SEQ / 64; kt++) {
        if (kt > 0) __syncthreads();   // previous PV reads of KV/P complete

        // Load K tile transposed into KV
        #pragma unroll
        for (int it = 0; it < 8; it++) {
            int d = lc0 + it * 16;
            float4 k = *(const float4*)&base[(size_t)(kt * 64 + lr) * QKV_N + DK + d];
            KV[(d + 0) * QS_STRIDE + lr] = k.x;
            KV[(d + 1) * QS_STRIDE + lr] = k.y;
            KV[(d + 2) * QS_STRIDE + lr] = k.z;
            KV[(d + 3) * QS_STRIDE + lr] = k.w;
        }
        __syncthreads();

        // Scores: 4x4 micro-tile, rows ty*4+i, cols tx*4+j
        float s[4][4];
        #pragma unroll
        for (int i = 0; i < 4; i++)
            #pragma unroll
            for (int j = 0; j < 4; j++) s[i][j] = 0.f;

        #pragma unroll 8
        for (int d = 0; d < 128; d++) {
            float4 qv = *(float4*)&Qs[d * QS_STRIDE + ty * 4];
            float4 kv = *(float4*)&KV[d * QS_STRIDE + tx * 4];
            float qa[4] = {qv.x, qv.y, qv.z, qv.w};
            float ka[4] = {kv.x, kv.y, kv.z, kv.w};
            #pragma unroll
            for (int i = 0; i < 4; i++)
                #pragma unroll
                for (int j = 0; j < 4; j++)
                    s[i][j] += qa[i] * ka[j];
        }

        // Online softmax update (row stats reduced across the 16 lanes sharing ty)
        float p[4][4];
        #pragma unroll
        for (int i = 0; i < 4; i++) {
            float mx = -1e30f;
            #pragma unroll
            for (int j = 0; j < 4; j++) { s[i][j] *= scale; mx = fmaxf(mx, s[i][j]); }
            #pragma unroll
            for (int off = 1; off < 16; off <<= 1)
                mx = fmaxf(mx, __shfl_xor_sync(0xffffffffu, mx, off));
            float mn = fmaxf(m[i], mx);
            float sum = 0.f;
            #pragma unroll
            for (int j = 0; j < 4; j++) { p[i][j] = __expf(s[i][j] - mn); sum += p[i][j]; }
            #pragma unroll
            for (int off = 1; off < 16; off <<= 1)
                sum += __shfl_xor_sync(0xffffffffu, sum, off);
            float alpha = __expf(m[i] - mn);
            l[i] = l[i] * alpha + sum;
            m[i] = mn;
            #pragma unroll
            for (int jd = 0; jd < 8; jd++) acc[i][jd] *= alpha;
        }
        __syncthreads();   // everyone done reading K before V overwrites KV

        // Store P (row-major [64][68]) and load V ([64][128]) into KV
        #pragma unroll
        for (int i = 0; i < 4; i++) {
            float4 pv = {p[i][0], p[i][1], p[i][2], p[i][3]};
            *(float4*)&P[(ty * 4 + i) * P_STRIDE + tx * 4] = pv;
        }
        #pragma unroll
        for (int it = 0; it < 8; it++) {
            int d = lc0 + it * 16;
            *(float4*)&KV[lr * 128 + d] =
                *(const float4*)&base[(size_t)(kt * 64 + lr) * QKV_N + 2 * DK + d];
        }
        __syncthreads();

        // PV accumulate: acc[i][jd] += P[row][k] * V[k][dim]
        #pragma unroll 8
        for (int k = 0; k < 64; k++) {
            float4 v0 = *(float4*)&KV[k * 128 + tx * 8];
            float4 v1 = *(float4*)&KV[k * 128 + tx * 8 + 4];
            float vv[8] = {v0.x, v0.y, v0.z, v0.w, v1.x, v1.y, v1.z, v1.w};
            #pragma unroll
            for (int i = 0; i < 4; i++) {
                float pi = P[(ty * 4 + i) * P_STRIDE + k];
                #pragma unroll
                for (int jd = 0; jd < 8; jd++)
                    acc[i][jd] += pi * vv[jd];
            }
        }
    }

    // Epilogue: normalize and write to [B*S, D_MODEL] at head column block
    #pragma unroll
    for (int i = 0; i < 4; i++) {
        float inv = 1.f / l[i];
        size_t row = (size_t)b * SEQ + q0 + ty * 4 + i;
        float4 o0 = {acc[i][0] * inv, acc[i][1] * inv, acc[i][2] * inv, acc[i][3] * inv};
        float4 o1 = {acc[i][4] * inv, acc[i][5] * inv, acc[i][6] * inv, acc[i][7] * inv};
        *(float4*)&out[row * D_MODEL + h * DK + tx * 8]     = o0;
        *(float4*)&out[row * D_MODEL + h * DK + tx * 8 + 4] = o1;
    }
}

// ---------------------------------------------------------------------------
extern "C" void kernel_launch(void* const* d_in, const int* in_sizes, int n_in,
                              void* d_out, int out_size)
{
    const float* x    = (const float*)d_in[0];
    const float* Wqkv = (const float*)d_in[1];
    const float* bqkv = (const float*)d_in[2];
    const float* Wout = (const float*)d_in[3];
    const float* bout = (const float*)d_in[4];
    float* out = (float*)d_out;

    float *qkv_ptr = nullptr, *att_ptr = nullptr;
    cudaGetSymbolAddress((void**)&qkv_ptr, g_qkv);
    cudaGetSymbolAddress((void**)&att_ptr, g_att);

    cudaFuncSetAttribute(attn_kernel,
                         cudaFuncAttributeMaxDynamicSharedMemorySize, ATTN_SMEM);

    dim3 blk(256);

    // 1) QKV projection: [4096,2048] @ [2048,6144] + b -> g_qkv
    sgemm_bias<<<dim3(QKV_N / 128, ROWS / 128), blk>>>(
        x, Wqkv, bqkv, qkv_ptr, ROWS, QKV_N, D_MODEL);

    // 2) Attention: flash-style per (b,h,q-tile) -> g_att [4096,2048]
    attn_kernel<<<dim3(SEQ / 64, BATCH * NHEADS), blk, ATTN_SMEM>>>(qkv_ptr, att_ptr);

    // 3) Output projection: [4096,2048] @ [2048,2048] + b -> d_out
    sgemm_bias<<<dim3(D_MODEL / 128, ROWS / 128), blk>>>(
        att_ptr, Wout, bout, out, ROWS, D_MODEL, D_MODEL);
}

// round 3
// speedup vs baseline: 1.6148x; 1.6148x over previous
#include <cuda_runtime.h>
#include <cuda_bf16.h>
#include <math.h>
#include <cstdint>

#define D_MODEL 2048
#define NHEADS  16
#define DK      128
#define BATCH   2
#define SEQ     2048
#define ROWS    (BATCH * SEQ)     // 4096
#define QKV_N   (3 * D_MODEL)     // 6144

// ---------------------------------------------------------------------------
// Scratch (device globals — no cudaMalloc allowed)
// ---------------------------------------------------------------------------
__device__ float g_qkv[ROWS * QKV_N];             // 100 MB fp32
__device__ float g_att[ROWS * D_MODEL];           // 33 MB fp32
__device__ __nv_bfloat16 g_a_hi[ROWS * D_MODEL];
__device__ __nv_bfloat16 g_a_lo[ROWS * D_MODEL];
__device__ __nv_bfloat16 g_wq_hi[QKV_N * D_MODEL];   // W_qkv^T [6144,2048]
__device__ __nv_bfloat16 g_wq_lo[QKV_N * D_MODEL];
__device__ __nv_bfloat16 g_wo_hi[D_MODEL * D_MODEL]; // W_out^T [2048,2048]
__device__ __nv_bfloat16 g_wo_lo[D_MODEL * D_MODEL];

// ---------------------------------------------------------------------------
// Base-target PTX helpers (NO tcgen05 — virtual target is compute_103)
// ---------------------------------------------------------------------------
__device__ __forceinline__ uint32_t smem_u32(const void* p) {
    uint32_t a;
    asm("{ .reg .u64 t; cvta.to.shared.u64 t, %1; cvt.u32.u64 %0, t; }" : "=r"(a) : "l"(p));
    return a;
}
__device__ __forceinline__ void cp_async16(uint32_t saddr, const void* gaddr) {
    asm volatile("cp.async.cg.shared.global [%0], [%1], 16;" :: "r"(saddr), "l"(gaddr));
}
#define CP_COMMIT() asm volatile("cp.async.commit_group;" ::: "memory")
#define CP_WAIT(N)  asm volatile("cp.async.wait_group %0;" :: "n"(N) : "memory")

__device__ __forceinline__ void ldmx4(uint32_t* r, uint32_t addr) {
    asm volatile("ldmatrix.sync.aligned.m8n8.x4.shared.b16 {%0,%1,%2,%3}, [%4];"
                 : "=r"(r[0]), "=r"(r[1]), "=r"(r[2]), "=r"(r[3]) : "r"(addr));
}
__device__ __forceinline__ void mma_bf16(float* d, const uint32_t* a, const uint32_t* b) {
    asm volatile(
        "mma.sync.aligned.m16n8k16.row.col.f32.bf16.bf16.f32 "
        "{%0,%1,%2,%3}, {%4,%5,%6,%7}, {%8,%9}, {%0,%1,%2,%3};"
        : "+f"(d[0]), "+f"(d[1]), "+f"(d[2]), "+f"(d[3])
        : "r"(a[0]), "r"(a[1]), "r"(a[2]), "r"(a[3]), "r"(b[0]), "r"(b[1]));
}

// smem tile layout: 128 rows x 32 bf16 (64B = 4 x 16B chunks), swizzled so
// ldmatrix phases (8 rows, fixed chunk) and (8 rows of same parity) are
// conflict-free:  chunk' = chunk ^ ((row>>1)&3)
__device__ __forceinline__ uint32_t sw_off(int r, int c) {
    return (uint32_t)(r * 64 + ((c ^ ((r >> 1) & 3)) << 4));
}

// ---------------------------------------------------------------------------
// fp32 -> bf16 hi/lo split
// ---------------------------------------------------------------------------
__global__ void split_kernel(const float* __restrict__ in,
                             __nv_bfloat16* __restrict__ hi,
                             __nv_bfloat16* __restrict__ lo, int n4)
{
    int i = blockIdx.x * blockDim.x + threadIdx.x;
    if (i >= n4) return;
    float4 v = ((const float4*)in)[i];
    __nv_bfloat16 h0 = __float2bfloat16(v.x), h1 = __float2bfloat16(v.y);
    __nv_bfloat16 h2 = __float2bfloat16(v.z), h3 = __float2bfloat16(v.w);
    __nv_bfloat16 l0 = __float2bfloat16(v.x - __bfloat162float(h0));
    __nv_bfloat16 l1 = __float2bfloat16(v.y - __bfloat162float(h1));
    __nv_bfloat16 l2 = __float2bfloat16(v.z - __bfloat162float(h2));
    __nv_bfloat16 l3 = __float2bfloat16(v.w - __bfloat162float(h3));
    ((__nv_bfloat162*)hi)[2*i]   = __halves2bfloat162(h0, h1);
    ((__nv_bfloat162*)hi)[2*i+1] = __halves2bfloat162(h2, h3);
    ((__nv_bfloat162*)lo)[2*i]   = __halves2bfloat162(l0, l1);
    ((__nv_bfloat162*)lo)[2*i+1] = __halves2bfloat162(l2, l3);
}

// W[K,N] fp32 -> Wt[N,K] bf16 hi/lo
__global__ void transpose_split_kernel(const float* __restrict__ W,
                                       __nv_bfloat16* __restrict__ Th,
                                       __nv_bfloat16* __restrict__ Tl,
                                       int K, int N)
{
    __shared__ float t[32][33];
    int k0 = blockIdx.y * 32, n0 = blockIdx.x * 32;
    #pragma unroll
    for (int i = threadIdx.y; i < 32; i += 8)
        t[i][threadIdx.x] = W[(size_t)(k0 + i) * N + n0 + threadIdx.x];
    __syncthreads();
    #pragma unroll
    for (int i = threadIdx.y; i < 32; i += 8) {
        float v = t[threadIdx.x][i];
        __nv_bfloat16 h = __float2bfloat16(v);
        __nv_bfloat16 l = __float2bfloat16(v - __bfloat162float(h));
        size_t o = (size_t)(n0 + i) * K + k0 + threadIdx.x;
        Th[o] = h;
        Tl[o] = l;
    }
}

// ---------------------------------------------------------------------------
// HMMA GEMM: C[M,N] = A[M,K] @ Bt[N,K]^T + bias  (bf16 hi/lo, fp32 acc)
// CTA 128x128, BK=32, 3-stage cp.async pipeline, 8 warps (4x2), warp 32x64.
// ---------------------------------------------------------------------------
#define GM_BK    32
#define STAGES   3
#define TILE_B   8192                       // one 128x32 bf16 tile
#define STAGE_B  (4 * TILE_B)               // Ahi | Alo | Bhi | Blo
#define GEMM_SMEM (STAGES * STAGE_B)        // 96 KB
#define OFF_AH 0
#define OFF_AL TILE_B
#define OFF_BH (2 * TILE_B)
#define OFF_BL (3 * TILE_B)

__global__ __launch_bounds__(256) void gemm_hmma(
    const __nv_bfloat16* __restrict__ Ah, const __nv_bfloat16* __restrict__ Al,
    const __nv_bfloat16* __restrict__ Bh, const __nv_bfloat16* __restrict__ Bl,
    const float* __restrict__ bias, float* __restrict__ C,
    int M, int N, int K)
{
    extern __shared__ char smc[];
    const uint32_t sb = smem_u32(smc);
    const int tid  = threadIdx.x;
    const int warp = tid >> 5, lane = tid & 31;
    const int wm = warp >> 1, wn = warp & 1;      // 4x2 warp grid
    const int bm = blockIdx.y, bn = blockIdx.x;
    const int NC = K / GM_BK;

    const __nv_bfloat16* gAh = Ah + (size_t)bm * 128 * K;
    const __nv_bfloat16* gAl = Al + (size_t)bm * 128 * K;
    const __nv_bfloat16* gBh = Bh + (size_t)bn * 128 * K;
    const __nv_bfloat16* gBl = Bl + (size_t)bn * 128 * K;

    // per-thread cp.async mapping: 512 chunks per tile, 2 iters of 256 threads
    const int r0 = tid >> 2, c0 = tid & 3;        // iter0: rows 0..63
    // iter1: rows 64..127 (idx + 256 -> r + 64)

    auto load_stage = [&](int chunk, int slot) {
        const int k0 = chunk * GM_BK;
        uint32_t base = sb + slot * STAGE_B;
        #pragma unroll
        for (int i = 0; i < 2; i++) {
            int r = r0 + i * 64;
            uint32_t so = sw_off(r, c0);
            size_t go = (size_t)r * K + k0 + c0 * 8;
            cp_async16(base + OFF_AH + so, gAh + go);
            cp_async16(base + OFF_AL + so, gAl + go);
            cp_async16(base + OFF_BH + so, gBh + go);
            cp_async16(base + OFF_BL + so, gBl + go);
        }
        CP_COMMIT();
    };

    float acc[2][8][4];
    #pragma unroll
    for (int mt = 0; mt < 2; mt++)
        #pragma unroll
        for (int nt = 0; nt < 8; nt++)
            #pragma unroll
            for (int j = 0; j < 4; j++) acc[mt][nt][j] = 0.f;

    // ldmatrix per-lane address components
    const int a_row = wm * 32 + (lane & 15);          // + mt*16
    const int a_cb  = (lane >> 4) & 1;                // chunk bit
    const int b_row = wn * 64 + (lane & 7) + ((lane & 16) ? 8 : 0);  // + pair*16
    const int b_cb  = (lane >> 3) & 1;

    // prologue
    #pragma unroll
    for (int s = 0; s < STAGES - 1; s++) load_stage(s, s);

    for (int c = 0; c < NC; c++) {
        if (c + STAGES - 1 < NC) { CP_WAIT(STAGES - 2); }
        else                     { CP_WAIT(0); }
        __syncthreads();

        const uint32_t base = sb + (c % STAGES) * STAGE_B;

        #pragma unroll
        for (int ks = 0; ks < 2; ks++) {
            uint32_t ahf[2][4], alf[2][4];
            #pragma unroll
            for (int mt = 0; mt < 2; mt++) {
                uint32_t so = sw_off(a_row + mt * 16, 2 * ks + a_cb);
                ldmx4(ahf[mt], base + OFF_AH + so);
                ldmx4(alf[mt], base + OFF_AL + so);
            }
            uint32_t bhf[8][2], blf[8][2];
            #pragma unroll
            for (int p = 0; p < 4; p++) {
                uint32_t so = sw_off(b_row + p * 16, 2 * ks + b_cb);
                uint32_t r[4];
                ldmx4(r, base + OFF_BH + so);
                bhf[2*p][0] = r[0]; bhf[2*p][1] = r[1];
                bhf[2*p+1][0] = r[2]; bhf[2*p+1][1] = r[3];
                ldmx4(r, base + OFF_BL + so);
                blf[2*p][0] = r[0]; blf[2*p][1] = r[1];
                blf[2*p+1][0] = r[2]; blf[2*p+1][1] = r[3];
            }
            #pragma unroll
            for (int mt = 0; mt < 2; mt++)
                #pragma unroll
                for (int nt = 0; nt < 8; nt++) {
                    mma_bf16(acc[mt][nt], ahf[mt], bhf[nt]);
                    mma_bf16(acc[mt][nt], ahf[mt], blf[nt]);
                    mma_bf16(acc[mt][nt], alf[mt], bhf[nt]);
                }
        }
        __syncthreads();
        if (c + STAGES - 1 < NC) load_stage(c + STAGES - 1, (c + STAGES - 1) % STAGES);
    }

    // epilogue
    const int erow = bm * 128 + wm * 32 + (lane >> 2);
    const int ecol = bn * 128 + wn * 64 + (lane & 3) * 2;
    #pragma unroll
    for (int mt = 0; mt < 2; mt++)
        #pragma unroll
        for (int nt = 0; nt < 8; nt++) {
            int col = ecol + nt * 8;
            float bx = bias[col], by = bias[col + 1];
            int ra = erow + mt * 16, rb = ra + 8;
            float2 o0 = {acc[mt][nt][0] + bx, acc[mt][nt][1] + by};
            float2 o1 = {acc[mt][nt][2] + bx, acc[mt][nt][3] + by};
            *(float2*)&C[(size_t)ra * N + col] = o0;
            *(float2*)&C[(size_t)rb * N + col] = o1;
        }
}

// ---------------------------------------------------------------------------
// Flash-style fp32 attention (unchanged — passes at 9e-7)
// ---------------------------------------------------------------------------
#define QS_STRIDE 68
#define P_STRIDE  68
#define ATTN_SMEM ((128 * QS_STRIDE + 128 * QS_STRIDE + 64 * P_STRIDE) * 4)

__global__ __launch_bounds__(256) void attn_kernel(
    const float* __restrict__ qkv, float* __restrict__ out)
{
    extern __shared__ float smf[];
    float* Qs = smf;
    float* KV = smf + 128 * QS_STRIDE;
    float* P  = smf + 2 * 128 * QS_STRIDE;

    const int tid = threadIdx.x;
    const int tx = tid & 15;
    const int ty = tid >> 4;
    const int qt = blockIdx.x;
    const int bh = blockIdx.y;
    const int b  = bh >> 4, h = bh & 15;

    const float* base = qkv + (size_t)b * SEQ * QKV_N + (size_t)h * (3 * DK);
    const int q0 = qt * 64;
    const int lr  = tid >> 2;
    const int lc0 = (tid & 3) * 4;

    #pragma unroll
    for (int it = 0; it < 8; it++) {
        int d = lc0 + it * 16;
        float4 q = *(const float4*)&base[(size_t)(q0 + lr) * QKV_N + d];
        Qs[(d + 0) * QS_STRIDE + lr] = q.x;
        Qs[(d + 1) * QS_STRIDE + lr] = q.y;
        Qs[(d + 2) * QS_STRIDE + lr] = q.z;
        Qs[(d + 3) * QS_STRIDE + lr] = q.w;
    }

    float m[4], l[4], acc[4][8];
    #pragma unroll
    for (int i = 0; i < 4; i++) {
        m[i] = -1e30f; l[i] = 0.f;
        #pragma unroll
        for (int j = 0; j < 8; j++) acc[i][j] = 0.f;
    }

    const float scale = 0.08838834764831845f;

    for (int kt = 0; kt < SEQ / 64; kt++) {
        if (kt > 0) __syncthreads();

        #pragma unroll
        for (int it = 0; it < 8; it++) {
            int d = lc0 + it * 16;
            float4 k = *(const float4*)&base[(size_t)(kt * 64 + lr) * QKV_N + DK + d];
            KV[(d + 0) * QS_STRIDE + lr] = k.x;
            KV[(d + 1) * QS_STRIDE + lr] = k.y;
            KV[(d + 2) * QS_STRIDE + lr] = k.z;
            KV[(d + 3) * QS_STRIDE + lr] = k.w;
        }
        __syncthreads();

        float s[4][4];
        #pragma unroll
        for (int i = 0; i < 4; i++)
            #pragma unroll
            for (int j = 0; j < 4; j++) s[i][j] = 0.f;

        #pragma unroll 8
        for (int d = 0; d < 128; d++) {
            float4 qv = *(float4*)&Qs[d * QS_STRIDE + ty * 4];
            float4 kv = *(float4*)&KV[d * QS_STRIDE + tx * 4];
            float qa[4] = {qv.x, qv.y, qv.z, qv.w};
            float ka[4] = {kv.x, kv.y, kv.z, kv.w};
            #pragma unroll
            for (int i = 0; i < 4; i++)
                #pragma unroll
                for (int j = 0; j < 4; j++)
                    s[i][j] += qa[i] * ka[j];
        }

        float p[4][4];
        #pragma unroll
        for (int i = 0; i < 4; i++) {
            float mx = -1e30f;
            #pragma unroll
            for (int j = 0; j < 4; j++) { s[i][j] *= scale; mx = fmaxf(mx, s[i][j]); }
            #pragma unroll
            for (int off = 1; off < 16; off <<= 1)
                mx = fmaxf(mx, __shfl_xor_sync(0xffffffffu, mx, off));
            float mn = fmaxf(m[i], mx);
            float sum = 0.f;
            #pragma unroll
            for (int j = 0; j < 4; j++) { p[i][j] = __expf(s[i][j] - mn); sum += p[i][j]; }
            #pragma unroll
            for (int off = 1; off < 16; off <<= 1)
                sum += __shfl_xor_sync(0xffffffffu, sum, off);
            float alpha = __expf(m[i] - mn);
            l[i] = l[i] * alpha + sum;
            m[i] = mn;
            #pragma unroll
            for (int jd = 0; jd < 8; jd++) acc[i][jd] *= alpha;
        }
        __syncthreads();

        #pragma unroll
        for (int i = 0; i < 4; i++) {
            float4 pv = {p[i][0], p[i][1], p[i][2], p[i][3]};
            *(float4*)&P[(ty * 4 + i) * P_STRIDE + tx * 4] = pv;
        }
        #pragma unroll
        for (int it = 0; it < 8; it++) {
            int d = lc0 + it * 16;
            *(float4*)&KV[lr * 128 + d] =
                *(const float4*)&base[(size_t)(kt * 64 + lr) * QKV_N + 2 * DK + d];
        }
        __syncthreads();

        #pragma unroll 8
        for (int k = 0; k < 64; k++) {
            float4 v0 = *(float4*)&KV[k * 128 + tx * 8];
            float4 v1 = *(float4*)&KV[k * 128 + tx * 8 + 4];
            float vv[8] = {v0.x, v0.y, v0.z, v0.w, v1.x, v1.y, v1.z, v1.w};
            #pragma unroll
            for (int i = 0; i < 4; i++) {
                float pi = P[(ty * 4 + i) * P_STRIDE + k];
                #pragma unroll
                for (int jd = 0; jd < 8; jd++)
                    acc[i][jd] += pi * vv[jd];
            }
        }
    }

    #pragma unroll
    for (int i = 0; i < 4; i++) {
        float inv = 1.f / l[i];
        size_t row = (size_t)b * SEQ + q0 + ty * 4 + i;
        float4 o0 = {acc[i][0] * inv, acc[i][1] * inv, acc[i][2] * inv, acc[i][3] * inv};
        float4 o1 = {acc[i][4] * inv, acc[i][5] * inv, acc[i][6] * inv, acc[i][7] * inv};
        *(float4*)&out[row * D_MODEL + h * DK + tx * 8]     = o0;
        *(float4*)&out[row * D_MODEL + h * DK + tx * 8 + 4] = o1;
    }
}

// ---------------------------------------------------------------------------
extern "C" void kernel_launch(void* const* d_in, const int* in_sizes, int n_in,
                              void* d_out, int out_size)
{
    const float* x    = (const float*)d_in[0];
    const float* Wqkv = (const float*)d_in[1];
    const float* bqkv = (const float*)d_in[2];
    const float* Wout = (const float*)d_in[3];
    const float* bout = (const float*)d_in[4];
    float* out = (float*)d_out;

    float *qkv_p, *att_p;
    __nv_bfloat16 *ah, *al, *wqh, *wql, *woh, *wol;
    cudaGetSymbolAddress((void**)&qkv_p, g_qkv);
    cudaGetSymbolAddress((void**)&att_p, g_att);
    cudaGetSymbolAddress((void**)&ah, g_a_hi);
    cudaGetSymbolAddress((void**)&al, g_a_lo);
    cudaGetSymbolAddress((void**)&wqh, g_wq_hi);
    cudaGetSymbolAddress((void**)&wql, g_wq_lo);
    cudaGetSymbolAddress((void**)&woh, g_wo_hi);
    cudaGetSymbolAddress((void**)&wol, g_wo_lo);

    cudaFuncSetAttribute(gemm_hmma, cudaFuncAttributeMaxDynamicSharedMemorySize, GEMM_SMEM);
    cudaFuncSetAttribute(attn_kernel, cudaFuncAttributeMaxDynamicSharedMemorySize, ATTN_SMEM);

    // 0) splits / transposes
    {
        int n4 = ROWS * D_MODEL / 4;
        split_kernel<<<(n4 + 255) / 256, 256>>>(x, ah, al, n4);
        transpose_split_kernel<<<dim3(QKV_N / 32, D_MODEL / 32), dim3(32, 8)>>>(
            Wqkv, wqh, wql, D_MODEL, QKV_N);
        transpose_split_kernel<<<dim3(D_MODEL / 32, D_MODEL / 32), dim3(32, 8)>>>(
            Wout, woh, wol, D_MODEL, D_MODEL);
    }

    // 1) QKV projection (HMMA): [4096,2048]@[2048,6144]+b -> g_qkv
    gemm_hmma<<<dim3(QKV_N / 128, ROWS / 128), 256, GEMM_SMEM>>>(
        ah, al, wqh, wql, bqkv, qkv_p, ROWS, QKV_N, D_MODEL);

    // 2) attention (fp32 flash) -> g_att
    attn_kernel<<<dim3(SEQ / 64, BATCH * NHEADS), 256, ATTN_SMEM>>>(qkv_p, att_p);

    // 3) split att output, out-projection (HMMA) -> d_out
    {
        int n4 = ROWS * D_MODEL / 4;
        split_kernel<<<(n4 + 255) / 256, 256>>>(att_p, ah, al, n4);
    }
    gemm_hmma<<<dim3(D_MODEL / 128, ROWS / 128), 256, GEMM_SMEM>>>(
        ah, al, woh, wol, bout, out, ROWS, D_MODEL, D_MODEL);
}

// round 4
// speedup vs baseline: 3.2619x; 2.0200x over previous
#include <cuda_runtime.h>
#include <cuda_bf16.h>
#include <math.h>
#include <cstdint>

#define D_MODEL 2048
#define NHEADS  16
#define DK      128
#define BATCH   2
#define SEQ     2048
#define ROWS    (BATCH * SEQ)     // 4096
#define QKV_N   (3 * D_MODEL)     // 6144

// ---------------------------------------------------------------------------
// Scratch (device globals — no cudaMalloc allowed)
// ---------------------------------------------------------------------------
__device__ __nv_bfloat16 g_qkv_hi[ROWS * QKV_N];     // 50 MB
__device__ __nv_bfloat16 g_qkv_lo[ROWS * QKV_N];
__device__ __nv_bfloat16 g_a_hi[ROWS * D_MODEL];     // x split, then attn out
__device__ __nv_bfloat16 g_a_lo[ROWS * D_MODEL];
__device__ __nv_bfloat16 g_wq_hi[QKV_N * D_MODEL];   // W_qkv^T [6144,2048]
__device__ __nv_bfloat16 g_wq_lo[QKV_N * D_MODEL];
__device__ __nv_bfloat16 g_wo_hi[D_MODEL * D_MODEL]; // W_out^T [2048,2048]
__device__ __nv_bfloat16 g_wo_lo[D_MODEL * D_MODEL];

// ---------------------------------------------------------------------------
// Base-target PTX helpers (virtual target is compute_103 — no tcgen05)
// ---------------------------------------------------------------------------
__device__ __forceinline__ uint32_t smem_u32(const void* p) {
    uint32_t a;
    asm("{ .reg .u64 t; cvta.to.shared.u64 t, %1; cvt.u32.u64 %0, t; }" : "=r"(a) : "l"(p));
    return a;
}
__device__ __forceinline__ void cp_async16(uint32_t saddr, const void* gaddr) {
    asm volatile("cp.async.cg.shared.global [%0], [%1], 16;" :: "r"(saddr), "l"(gaddr));
}
#define CP_COMMIT() asm volatile("cp.async.commit_group;" ::: "memory")
#define CP_WAIT(N)  asm volatile("cp.async.wait_group %0;" :: "n"(N) : "memory")

__device__ __forceinline__ void ldmx4(uint32_t* r, uint32_t addr) {
    asm volatile("ldmatrix.sync.aligned.m8n8.x4.shared.b16 {%0,%1,%2,%3}, [%4];"
                 : "=r"(r[0]), "=r"(r[1]), "=r"(r[2]), "=r"(r[3]) : "r"(addr));
}
__device__ __forceinline__ void ldmx4t(uint32_t* r, uint32_t addr) {
    asm volatile("ldmatrix.sync.aligned.m8n8.x4.trans.shared.b16 {%0,%1,%2,%3}, [%4];"
                 : "=r"(r[0]), "=r"(r[1]), "=r"(r[2]), "=r"(r[3]) : "r"(addr));
}
__device__ __forceinline__ void mma_bf16(float* d, const uint32_t* a, const uint32_t* b) {
    asm volatile(
        "mma.sync.aligned.m16n8k16.row.col.f32.bf16.bf16.f32 "
        "{%0,%1,%2,%3}, {%4,%5,%6,%7}, {%8,%9}, {%0,%1,%2,%3};"
        : "+f"(d[0]), "+f"(d[1]), "+f"(d[2]), "+f"(d[3])
        : "r"(a[0]), "r"(a[1]), "r"(a[2]), "r"(a[3]), "r"(b[0]), "r"(b[1]));
}

// pack 2 floats into bf16x2 hi + bf16x2 residual-lo
__device__ __forceinline__ void split2(float x, float y, uint32_t& h, uint32_t& l) {
    __nv_bfloat16 hx = __float2bfloat16(x), hy = __float2bfloat16(y);
    __nv_bfloat16 lx = __float2bfloat16(x - __bfloat162float(hx));
    __nv_bfloat16 ly = __float2bfloat16(y - __bfloat162float(hy));
    __nv_bfloat162 hh = __halves2bfloat162(hx, hy);
    __nv_bfloat162 ll = __halves2bfloat162(lx, ly);
    h = *(uint32_t*)&hh;
    l = *(uint32_t*)&ll;
}

// GEMM smem tile: rows of 32 bf16 (64B = 4 x 16B chunks): chunk ^= (row>>1)&3
__device__ __forceinline__ uint32_t sw_off(int r, int c) {
    return (uint32_t)(r * 64 + ((c ^ ((r >> 1) & 3)) << 4));
}
// Attention smem tile: rows of 128 bf16 (256B = 16 x 16B chunks): chunk ^= row&7
__device__ __forceinline__ uint32_t asw(int row, int ch) {
    return (uint32_t)(row * 256 + ((ch ^ (row & 7)) << 4));
}

// ---------------------------------------------------------------------------
// fp32 -> bf16 hi/lo split (x only)
// ---------------------------------------------------------------------------
__global__ void split_kernel(const float* __restrict__ in,
                             __nv_bfloat16* __restrict__ hi,
                             __nv_bfloat16* __restrict__ lo, int n4)
{
    int i = blockIdx.x * blockDim.x + threadIdx.x;
    if (i >= n4) return;
    float4 v = ((const float4*)in)[i];
    uint32_t h0, l0, h1, l1;
    split2(v.x, v.y, h0, l0);
    split2(v.z, v.w, h1, l1);
    ((uint32_t*)hi)[2*i]   = h0;
    ((uint32_t*)hi)[2*i+1] = h1;
    ((uint32_t*)lo)[2*i]   = l0;
    ((uint32_t*)lo)[2*i+1] = l1;
}

// W[K,N] fp32 -> Wt[N,K] bf16 hi/lo
__global__ void transpose_split_kernel(const float* __restrict__ W,
                                       __nv_bfloat16* __restrict__ Th,
                                       __nv_bfloat16* __restrict__ Tl,
                                       int K, int N)
{
    __shared__ float t[32][33];
    int k0 = blockIdx.y * 32, n0 = blockIdx.x * 32;
    #pragma unroll
    for (int i = threadIdx.y; i < 32; i += 8)
        t[i][threadIdx.x] = W[(size_t)(k0 + i) * N + n0 + threadIdx.x];
    __syncthreads();
    #pragma unroll
    for (int i = threadIdx.y; i < 32; i += 8) {
        float v = t[threadIdx.x][i];
        __nv_bfloat16 h = __float2bfloat16(v);
        __nv_bfloat16 l = __float2bfloat16(v - __bfloat162float(h));
        size_t o = (size_t)(n0 + i) * K + k0 + threadIdx.x;
        Th[o] = h;
        Tl[o] = l;
    }
}

// ---------------------------------------------------------------------------
// HMMA GEMM: C[M,N] = A[M,K] @ Bt[N,K]^T + bias  (bf16 hi/lo, fp32 acc)
// CTA 128x128, BK=32, 3-stage cp.async pipeline, 8 warps (4x2), warp 32x64.
// SPLIT=true: write bf16 hi/lo C; SPLIT=false: write fp32 C.
// ---------------------------------------------------------------------------
#define GM_BK    32
#define STAGES   3
#define TILE_B   8192
#define STAGE_B  (4 * TILE_B)
#define GEMM_SMEM (STAGES * STAGE_B)        // 96 KB
#define OFF_AH 0
#define OFF_AL TILE_B
#define OFF_BH (2 * TILE_B)
#define OFF_BL (3 * TILE_B)

template<bool SPLIT>
__global__ __launch_bounds__(256) void gemm_hmma(
    const __nv_bfloat16* __restrict__ Ah, const __nv_bfloat16* __restrict__ Al,
    const __nv_bfloat16* __restrict__ Bh, const __nv_bfloat16* __restrict__ Bl,
    const float* __restrict__ bias, float* __restrict__ C,
    __nv_bfloat16* __restrict__ Ch, __nv_bfloat16* __restrict__ Cl,
    int M, int N, int K)
{
    extern __shared__ char smc[];
    const uint32_t sb = smem_u32(smc);
    const int tid  = threadIdx.x;
    const int warp = tid >> 5, lane = tid & 31;
    const int wm = warp >> 1, wn = warp & 1;
    const int bm = blockIdx.y, bn = blockIdx.x;
    const int NC = K / GM_BK;

    const __nv_bfloat16* gAh = Ah + (size_t)bm * 128 * K;
    const __nv_bfloat16* gAl = Al + (size_t)bm * 128 * K;
    const __nv_bfloat16* gBh = Bh + (size_t)bn * 128 * K;
    const __nv_bfloat16* gBl = Bl + (size_t)bn * 128 * K;

    const int r0 = tid >> 2, c0 = tid & 3;

    auto load_stage = [&](int chunk, int slot) {
        const int k0 = chunk * GM_BK;
        uint32_t base = sb + slot * STAGE_B;
        #pragma unroll
        for (int i = 0; i < 2; i++) {
            int r = r0 + i * 64;
            uint32_t so = sw_off(r, c0);
            size_t go = (size_t)r * K + k0 + c0 * 8;
            cp_async16(base + OFF_AH + so, gAh + go);
            cp_async16(base + OFF_AL + so, gAl + go);
            cp_async16(base + OFF_BH + so, gBh + go);
            cp_async16(base + OFF_BL + so, gBl + go);
        }
        CP_COMMIT();
    };

    float acc[2][8][4];
    #pragma unroll
    for (int mt = 0; mt < 2; mt++)
        #pragma unroll
        for (int nt = 0; nt < 8; nt++)
            #pragma unroll
            for (int j = 0; j < 4; j++) acc[mt][nt][j] = 0.f;

    const int a_row = wm * 32 + (lane & 15);
    const int a_cb  = (lane >> 4) & 1;
    const int b_row = wn * 64 + (lane & 7) + ((lane & 16) ? 8 : 0);
    const int b_cb  = (lane >> 3) & 1;

    #pragma unroll
    for (int s = 0; s < STAGES - 1; s++) load_stage(s, s);

    for (int c = 0; c < NC; c++) {
        if (c + STAGES - 1 < NC) { CP_WAIT(STAGES - 2); }
        else                     { CP_WAIT(0); }
        __syncthreads();

        const uint32_t base = sb + (c % STAGES) * STAGE_B;

        #pragma unroll
        for (int ks = 0; ks < 2; ks++) {
            uint32_t ahf[2][4], alf[2][4];
            #pragma unroll
            for (int mt = 0; mt < 2; mt++) {
                uint32_t so = sw_off(a_row + mt * 16, 2 * ks + a_cb);
                ldmx4(ahf[mt], base + OFF_AH + so);
                ldmx4(alf[mt], base + OFF_AL + so);
            }
            uint32_t bhf[8][2], blf[8][2];
            #pragma unroll
            for (int p = 0; p < 4; p++) {
                uint32_t so = sw_off(b_row + p * 16, 2 * ks + b_cb);
                uint32_t r[4];
                ldmx4(r, base + OFF_BH + so);
                bhf[2*p][0] = r[0]; bhf[2*p][1] = r[1];
                bhf[2*p+1][0] = r[2]; bhf[2*p+1][1] = r[3];
                ldmx4(r, base + OFF_BL + so);
                blf[2*p][0] = r[0]; blf[2*p][1] = r[1];
                blf[2*p+1][0] = r[2]; blf[2*p+1][1] = r[3];
            }
            #pragma unroll
            for (int mt = 0; mt < 2; mt++)
                #pragma unroll
                for (int nt = 0; nt < 8; nt++) {
                    mma_bf16(acc[mt][nt], ahf[mt], bhf[nt]);
                    mma_bf16(acc[mt][nt], ahf[mt], blf[nt]);
                    mma_bf16(acc[mt][nt], alf[mt], bhf[nt]);
                }
        }
        __syncthreads();
        if (c + STAGES - 1 < NC) load_stage(c + STAGES - 1, (c + STAGES - 1) % STAGES);
    }

    const int erow = bm * 128 + wm * 32 + (lane >> 2);
    const int ecol = bn * 128 + wn * 64 + (lane & 3) * 2;
    #pragma unroll
    for (int mt = 0; mt < 2; mt++)
        #pragma unroll
        for (int nt = 0; nt < 8; nt++) {
            int col = ecol + nt * 8;
            float bx = bias[col], by = bias[col + 1];
            int ra = erow + mt * 16, rb = ra + 8;
            float v0 = acc[mt][nt][0] + bx, v1 = acc[mt][nt][1] + by;
            float v2 = acc[mt][nt][2] + bx, v3 = acc[mt][nt][3] + by;
            if (SPLIT) {
                uint32_t hh, ll;
                split2(v0, v1, hh, ll);
                *(uint32_t*)&Ch[(size_t)ra * N + col] = hh;
                *(uint32_t*)&Cl[(size_t)ra * N + col] = ll;
                split2(v2, v3, hh, ll);
                *(uint32_t*)&Ch[(size_t)rb * N + col] = hh;
                *(uint32_t*)&Cl[(size_t)rb * N + col] = ll;
            } else {
                float2 o0 = {v0, v1}, o1 = {v2, v3};
                *(float2*)&C[(size_t)ra * N + col] = o0;
                *(float2*)&C[(size_t)rb * N + col] = o1;
            }
        }
}

// ---------------------------------------------------------------------------
// HMMA flash attention (bf16 hi/lo, 3 products each GEMM, fp32 softmax)
// CTA: 128 q rows of one (b,h); 8 warps x 16 rows; 64-key tiles, double buffer.
// ---------------------------------------------------------------------------
#define AT_BQ 128
#define AT_BK 64
#define AT_NT (SEQ / AT_BK)          // 32
#define AQ_H 0
#define AQ_L 32768
#define AST(s) (65536 + (s) * 65536)
#define AK_H 0
#define AK_L 16384
#define AV_H 32768
#define AV_L 49152
#define ATTN_SMEM (65536 + 2 * 65536)   // 192 KB

__global__ __launch_bounds__(256, 1) void attn_hmma(
    const __nv_bfloat16* __restrict__ qh_g, const __nv_bfloat16* __restrict__ ql_g,
    __nv_bfloat16* __restrict__ oh_g, __nv_bfloat16* __restrict__ ol_g)
{
    extern __shared__ char smc[];
    const uint32_t sb = smem_u32(smc);
    const int tid = threadIdx.x, warp = tid >> 5, lane = tid & 31;
    const int qt = blockIdx.x, bh = blockIdx.y;
    const int b = bh >> 4, h = bh & 15;
    const size_t tok0  = (size_t)b * SEQ + qt * AT_BQ;
    const size_t ktok0 = (size_t)b * SEQ;
    const int colQ = h * 3 * DK, colK = colQ + DK, colV = colQ + 2 * DK;
    const float SCALE = 0.08838834764831845f;

    auto loadQ = [&]() {
        #pragma unroll
        for (int i = 0; i < 8; i++) {
            int idx = tid + i * 256;
            int r = idx >> 4, ch = idx & 15;
            uint32_t so = asw(r, ch);
            size_t g = (tok0 + r) * QKV_N + colQ + ch * 8;
            cp_async16(sb + AQ_H + so, qh_g + g);
            cp_async16(sb + AQ_L + so, ql_g + g);
        }
        CP_COMMIT();
    };
    auto loadK = [&](int kt, int s) {
        #pragma unroll
        for (int i = 0; i < 4; i++) {
            int idx = tid + i * 256;
            int r = idx >> 4, ch = idx & 15;
            uint32_t so = asw(r, ch);
            size_t g = (ktok0 + kt * AT_BK + r) * QKV_N + colK + ch * 8;
            cp_async16(sb + AST(s) + AK_H + so, qh_g + g);
            cp_async16(sb + AST(s) + AK_L + so, ql_g + g);
        }
        CP_COMMIT();
    };
    auto loadV = [&](int kt, int s) {
        #pragma unroll
        for (int i = 0; i < 4; i++) {
            int idx = tid + i * 256;
            int r = idx >> 4, ch = idx & 15;
            uint32_t so = asw(r, ch);
            size_t g = (ktok0 + kt * AT_BK + r) * QKV_N + colV + ch * 8;
            cp_async16(sb + AST(s) + AV_H + so, qh_g + g);
            cp_async16(sb + AST(s) + AV_L + so, ql_g + g);
        }
        CP_COMMIT();
    };

    // ldmatrix lane address components
    const int aq_row = warp * 16 + (lane & 15);       // Q (A operand)
    const int a_cb   = lane >> 4;
    const int bk_row = (lane & 7) + ((lane & 16) ? 8 : 0);   // K (B operand)
    const int bk_cb  = (lane >> 3) & 1;
    const int v_row  = (lane & 7) + (((lane >> 3) & 1) << 3); // V (trans B)
    const int v_cb   = lane >> 4;

    float oacc[16][4];
    #pragma unroll
    for (int n = 0; n < 16; n++)
        #pragma unroll
        for (int j = 0; j < 4; j++) oacc[n][j] = 0.f;
    float m0 = -1e30f, m1 = -1e30f, l0 = 0.f, l1 = 0.f;

    // prologue: Q, K0, V0, K1  (4 groups outstanding)
    loadQ();
    loadK(0, 0);
    loadV(0, 0);
    loadK(1, 1);

    for (int kt = 0; kt < AT_NT; kt++) {
        const int cur = kt & 1;

        CP_WAIT(2);              // K_kt (and Q on kt=0) complete
        __syncthreads();
        const uint32_t kb = sb + AST(cur);

        // ---- S = Q K^T (3 products) ----
        float sacc[8][4];
        #pragma unroll
        for (int n = 0; n < 8; n++)
            #pragma unroll
            for (int j = 0; j < 4; j++) sacc[n][j] = 0.f;

        #pragma unroll
        for (int ks = 0; ks < 8; ks++) {
            uint32_t qh4[4], ql4[4];
            uint32_t qso = asw(aq_row, 2 * ks + a_cb);
            ldmx4(qh4, sb + AQ_H + qso);
            ldmx4(ql4, sb + AQ_L + qso);
            #pragma unroll
            for (int p = 0; p < 4; p++) {
                uint32_t kh4[4], kl4[4];
                uint32_t kso = asw(p * 16 + bk_row, 2 * ks + bk_cb);
                ldmx4(kh4, kb + AK_H + kso);
                ldmx4(kl4, kb + AK_L + kso);
                mma_bf16(sacc[2*p],   qh4, kh4);
                mma_bf16(sacc[2*p+1], qh4, kh4 + 2);
                mma_bf16(sacc[2*p],   qh4, kl4);
                mma_bf16(sacc[2*p+1], qh4, kl4 + 2);
                mma_bf16(sacc[2*p],   ql4, kh4);
                mma_bf16(sacc[2*p+1], ql4, kh4 + 2);
            }
        }

        // prefetch next V (wrap-around dummy keeps wait-counts exact)
        loadV((kt + 1) % AT_NT, cur ^ 1);

        // ---- online softmax on S fragments ----
        float mx0 = -1e30f, mx1 = -1e30f;
        #pragma unroll
        for (int n = 0; n < 8; n++) {
            sacc[n][0] *= SCALE; sacc[n][1] *= SCALE;
            sacc[n][2] *= SCALE; sacc[n][3] *= SCALE;
            mx0 = fmaxf(mx0, fmaxf(sacc[n][0], sacc[n][1]));
            mx1 = fmaxf(mx1, fmaxf(sacc[n][2], sacc[n][3]));
        }
        mx0 = fmaxf(mx0, __shfl_xor_sync(0xffffffffu, mx0, 1));
        mx0 = fmaxf(mx0, __shfl_xor_sync(0xffffffffu, mx0, 2));
        mx1 = fmaxf(mx1, __shfl_xor_sync(0xffffffffu, mx1, 1));
        mx1 = fmaxf(mx1, __shfl_xor_sync(0xffffffffu, mx1, 2));
        const float mn0 = fmaxf(m0, mx0), mn1 = fmaxf(m1, mx1);

        float sum0 = 0.f, sum1 = 0.f;
        uint32_t ph[8][2], pl[8][2];
        #pragma unroll
        for (int n = 0; n < 8; n++) {
            float p00 = __expf(sacc[n][0] - mn0), p01 = __expf(sacc[n][1] - mn0);
            float p10 = __expf(sacc[n][2] - mn1), p11 = __expf(sacc[n][3] - mn1);
            sum0 += p00 + p01;
            sum1 += p10 + p11;
            split2(p00, p01, ph[n][0], pl[n][0]);
            split2(p10, p11, ph[n][1], pl[n][1]);
        }
        sum0 += __shfl_xor_sync(0xffffffffu, sum0, 1);
        sum0 += __shfl_xor_sync(0xffffffffu, sum0, 2);
        sum1 += __shfl_xor_sync(0xffffffffu, sum1, 1);
        sum1 += __shfl_xor_sync(0xffffffffu, sum1, 2);

        const float al0 = __expf(m0 - mn0), al1 = __expf(m1 - mn1);
        m0 = mn0; m1 = mn1;
        l0 = l0 * al0 + sum0;
        l1 = l1 * al1 + sum1;
        #pragma unroll
        for (int n = 0; n < 16; n++) {
            oacc[n][0] *= al0; oacc[n][1] *= al0;
            oacc[n][2] *= al1; oacc[n][3] *= al1;
        }

        CP_WAIT(2);              // V_kt complete
        __syncthreads();
        const uint32_t vb = sb + AST(cur);

        // ---- O += P V (3 products) ----
        #pragma unroll
        for (int kk = 0; kk < 4; kk++) {
            uint32_t pah[4] = {ph[2*kk][0], ph[2*kk][1], ph[2*kk+1][0], ph[2*kk+1][1]};
            uint32_t pal[4] = {pl[2*kk][0], pl[2*kk][1], pl[2*kk+1][0], pl[2*kk+1][1]};
            #pragma unroll
            for (int p = 0; p < 8; p++) {
                uint32_t vh4[4], vl4[4];
                uint32_t vso = asw(kk * 16 + v_row, 2 * p + v_cb);
                ldmx4t(vh4, vb + AV_H + vso);
                ldmx4t(vl4, vb + AV_L + vso);
                mma_bf16(oacc[2*p],   pah, vh4);
                mma_bf16(oacc[2*p+1], pah, vh4 + 2);
                mma_bf16(oacc[2*p],   pah, vl4);
                mma_bf16(oacc[2*p+1], pah, vl4 + 2);
                mma_bf16(oacc[2*p],   pal, vh4);
                mma_bf16(oacc[2*p+1], pal, vh4 + 2);
            }
        }

        // prefetch K two tiles ahead (wrap-around dummy)
        loadK((kt + 2) % AT_NT, cur);
    }

    // ---- epilogue: normalize, split hi/lo, write [ROWS, D_MODEL] slice ----
    const float inv0 = 1.f / l0, inv1 = 1.f / l1;
    const int rr = lane >> 2, c2 = (lane & 3) * 2;
    const size_t row0 = tok0 + warp * 16 + rr, row1 = row0 + 8;
    #pragma unroll
    for (int n = 0; n < 16; n++) {
        int col = h * DK + n * 8 + c2;
        uint32_t hh, ll;
        split2(oacc[n][0] * inv0, oacc[n][1] * inv0, hh, ll);
        *(uint32_t*)&oh_g[row0 * D_MODEL + col] = hh;
        *(uint32_t*)&ol_g[row0 * D_MODEL + col] = ll;
        split2(oacc[n][2] * inv1, oacc[n][3] * inv1, hh, ll);
        *(uint32_t*)&oh_g[row1 * D_MODEL + col] = hh;
        *(uint32_t*)&ol_g[row1 * D_MODEL + col] = ll;
    }
}

// ---------------------------------------------------------------------------
extern "C" void kernel_launch(void* const* d_in, const int* in_sizes, int n_in,
                              void* d_out, int out_size)
{
    const float* x    = (const float*)d_in[0];
    const float* Wqkv = (const float*)d_in[1];
    const float* bqkv = (const float*)d_in[2];
    const float* Wout = (const float*)d_in[3];
    const float* bout = (const float*)d_in[4];
    float* out = (float*)d_out;

    __nv_bfloat16 *qkh, *qkl, *ah, *al, *wqh, *wql, *woh, *wol;
    cudaGetSymbolAddress((void**)&qkh, g_qkv_hi);
    cudaGetSymbolAddress((void**)&qkl, g_qkv_lo);
    cudaGetSymbolAddress((void**)&ah, g_a_hi);
    cudaGetSymbolAddress((void**)&al, g_a_lo);
    cudaGetSymbolAddress((void**)&wqh, g_wq_hi);
    cudaGetSymbolAddress((void**)&wql, g_wq_lo);
    cudaGetSymbolAddress((void**)&woh, g_wo_hi);
    cudaGetSymbolAddress((void**)&wol, g_wo_lo);

    cudaFuncSetAttribute(gemm_hmma<true>,  cudaFuncAttributeMaxDynamicSharedMemorySize, GEMM_SMEM);
    cudaFuncSetAttribute(gemm_hmma<false>, cudaFuncAttributeMaxDynamicSharedMemorySize, GEMM_SMEM);
    cudaFuncSetAttribute(attn_hmma, cudaFuncAttributeMaxDynamicSharedMemorySize, ATTN_SMEM);

    // 0) split x; transpose+split weights
    {
        int n4 = ROWS * D_MODEL / 4;
        split_kernel<<<(n4 + 255) / 256, 256>>>(x, ah, al, n4);
        transpose_split_kernel<<<dim3(QKV_N / 32, D_MODEL / 32), dim3(32, 8)>>>(
            Wqkv, wqh, wql, D_MODEL, QKV_N);
        transpose_split_kernel<<<dim3(D_MODEL / 32, D_MODEL / 32), dim3(32, 8)>>>(
            Wout, woh, wol, D_MODEL, D_MODEL);
    }

    // 1) QKV projection (HMMA), epilogue writes bf16 hi/lo
    gemm_hmma<true><<<dim3(QKV_N / 128, ROWS / 128), 256, GEMM_SMEM>>>(
        ah, al, wqh, wql, bqkv, nullptr, qkh, qkl, ROWS, QKV_N, D_MODEL);

    // 2) attention (HMMA flash), epilogue writes bf16 hi/lo into a_hi/a_lo
    attn_hmma<<<dim3(SEQ / AT_BQ, BATCH * NHEADS), 256, ATTN_SMEM>>>(qkh, qkl, ah, al);

    // 3) out-projection (HMMA), fp32 output
    gemm_hmma<false><<<dim3(D_MODEL / 128, ROWS / 128), 256, GEMM_SMEM>>>(
        ah, al, woh, wol, bout, out, nullptr, nullptr, ROWS, D_MODEL, D_MODEL);
}